// round 1
// baseline (speedup 1.0000x reference)
#include <cuda_runtime.h>
#include <math.h>

#define B_ 2
#define N_ 2048
#define D_ 768
#define H_ 12
#define HD_ 64
#define QKVSTRIDE (3 * D_)   // 2304

// Scratch (allocation-free): qkv projection result and attention output.
__device__ float g_qkv[(size_t)B_ * N_ * 3 * D_];   // (B, N, 3*D)
__device__ float g_ao [(size_t)B_ * N_ * D_];       // (B, N, D)

// ---------------------------------------------------------------------------
// NT SGEMM: C[M, Nc] = A[M, K] @ W[Nc, K]^T (+ bias).  64x64x16 tiles,
// 256 threads, 4x4 micro-tile per thread. Smem staged transposed so compute
// reads are float4 / broadcast, conflict-free.
// ---------------------------------------------------------------------------
template <bool BIAS, bool TO_QKV>
__global__ __launch_bounds__(256) void gemm_nt_kernel(
    const float* __restrict__ A, const float* __restrict__ W,
    const float* __restrict__ bias, float* __restrict__ C,
    int M, int Nc, int K)
{
    const int BM = 64, BN = 64, BK = 16;
    __shared__ float As[BK][BM + 4];
    __shared__ float Ws[BK][BN + 4];

    const int t  = threadIdx.x;
    const int tx = t & 15;
    const int ty = t >> 4;
    const int m0 = blockIdx.y * BM;
    const int n0 = blockIdx.x * BN;

    float acc[4][4];
#pragma unroll
    for (int i = 0; i < 4; i++)
#pragma unroll
        for (int j = 0; j < 4; j++) acc[i][j] = 0.f;

    const int rowL = t >> 2;         // 0..63
    const int k4   = (t & 3) * 4;    // 0,4,8,12

    const float* Ap = A + (size_t)(m0 + rowL) * K + k4;
    const float* Wp = W + (size_t)(n0 + rowL) * K + k4;

    for (int kk = 0; kk < K; kk += BK) {
        float4 va = *(const float4*)(Ap + kk);
        float4 vw = *(const float4*)(Wp + kk);
        As[k4 + 0][rowL] = va.x; As[k4 + 1][rowL] = va.y;
        As[k4 + 2][rowL] = va.z; As[k4 + 3][rowL] = va.w;
        Ws[k4 + 0][rowL] = vw.x; Ws[k4 + 1][rowL] = vw.y;
        Ws[k4 + 2][rowL] = vw.z; Ws[k4 + 3][rowL] = vw.w;
        __syncthreads();
#pragma unroll
        for (int k = 0; k < BK; k++) {
            float4 a = *(const float4*)&As[k][ty * 4];
            float4 b = *(const float4*)&Ws[k][tx * 4];
            float av[4] = {a.x, a.y, a.z, a.w};
            float bv[4] = {b.x, b.y, b.z, b.w};
#pragma unroll
            for (int i = 0; i < 4; i++)
#pragma unroll
                for (int j = 0; j < 4; j++)
                    acc[i][j] = fmaf(av[i], bv[j], acc[i][j]);
        }
        __syncthreads();
    }

#pragma unroll
    for (int i = 0; i < 4; i++) {
        int m = m0 + ty * 4 + i;
#pragma unroll
        for (int j = 0; j < 4; j++) {
            int n = n0 + tx * 4 + j;
            float v = acc[i][j];
            if (BIAS) v += bias[n];
            C[(size_t)m * Nc + n] = v;
        }
    }
    (void)TO_QKV;
}

// ---------------------------------------------------------------------------
// RoPE applied in-place to q and k slices of g_qkv.
// thetas: pos_embed (N, HD). x1 = dims [0,32), x2 = dims [32,64).
// out[d]    = x1*cos(th[d])    - x2*sin(th[d])
// out[d+32] = x2*cos(th[d+32]) + x1*sin(th[d+32])
// ---------------------------------------------------------------------------
__global__ void rope_kernel(const float* __restrict__ pe)
{
    int idx = blockIdx.x * blockDim.x + threadIdx.x;
    const int total = B_ * N_ * 2 * H_ * 32;
    if (idx >= total) return;
    int d = idx & 31;  int r = idx >> 5;
    int h = r % H_;    r /= H_;
    int c = r & 1;     r >>= 1;
    int n = r % N_;    int b = r / N_;

    float* p = g_qkv + (size_t)(b * N_ + n) * QKVSTRIDE + c * D_ + h * HD_;
    float x1 = p[d];
    float x2 = p[d + 32];
    float s1, c1, s2, c2;
    sincosf(pe[n * HD_ + d],      &s1, &c1);
    sincosf(pe[n * HD_ + d + 32], &s2, &c2);
    p[d]      = x1 * c1 - x2 * s1;
    p[d + 32] = x2 * c2 + x1 * s2;
}

// ---------------------------------------------------------------------------
// Flash-style attention. One CTA = 64 queries of one (b, h).
// 256 threads as 16x16; each thread owns a 4x4 micro-tile.
// Online softmax over 32 key tiles of 64.
// Dynamic smem: Qt[64][68] (d-major), Kt[64][68] (d-major),
//               Vs[64][68] (k-major), Ps[64][65] (k-major, P^T).
// ---------------------------------------------------------------------------
__global__ __launch_bounds__(256) void attn_kernel()
{
    extern __shared__ float sm[];
    float* Qt = sm;                  // [d][q], stride 68
    float* Kt = Qt + 64 * 68;        // [d][k], stride 68
    float* Vs = Kt + 64 * 68;        // [k][d], stride 68
    float* Ps = Vs + 64 * 68;        // [k][q], stride 65

    const int t  = threadIdx.x;
    const int tx = t & 15;
    const int ty = t >> 4;
    const int bh = blockIdx.y;
    const int b  = bh / H_;
    const int h  = bh % H_;
    const int q0 = blockIdx.x * 64;

    const float* qbase = g_qkv + (size_t)b * N_ * QKVSTRIDE + h * HD_;
    const float* kbase = qbase + D_;
    const float* vbase = qbase + 2 * D_;

    const int lrow = t >> 4;       // 0..15
    const int d4   = (t & 15) * 4; // 0..60

    // Load Q tile, scaled by 1/sqrt(HD), transposed into Qt[d][q].
#pragma unroll
    for (int it = 0; it < 4; it++) {
        int row = lrow + it * 16;
        float4 qv = *(const float4*)(qbase + (size_t)(q0 + row) * QKVSTRIDE + d4);
        Qt[(d4 + 0) * 68 + row] = qv.x * 0.125f;
        Qt[(d4 + 1) * 68 + row] = qv.y * 0.125f;
        Qt[(d4 + 2) * 68 + row] = qv.z * 0.125f;
        Qt[(d4 + 3) * 68 + row] = qv.w * 0.125f;
    }

    float accO[4][4];
    float mrow[4], lsum[4];
#pragma unroll
    for (int i = 0; i < 4; i++) {
        mrow[i] = -1e30f;
        lsum[i] = 0.f;
#pragma unroll
        for (int j = 0; j < 4; j++) accO[i][j] = 0.f;
    }

    for (int kt = 0; kt < N_ / 64; kt++) {
        const int k0 = kt * 64;
        // Load K (transposed) and V tiles.
#pragma unroll
        for (int it = 0; it < 4; it++) {
            int row = lrow + it * 16;
            float4 kv = *(const float4*)(kbase + (size_t)(k0 + row) * QKVSTRIDE + d4);
            Kt[(d4 + 0) * 68 + row] = kv.x;
            Kt[(d4 + 1) * 68 + row] = kv.y;
            Kt[(d4 + 2) * 68 + row] = kv.z;
            Kt[(d4 + 3) * 68 + row] = kv.w;
            float4 vv = *(const float4*)(vbase + (size_t)(k0 + row) * QKVSTRIDE + d4);
            *(float4*)&Vs[row * 68 + d4] = vv;
        }
        __syncthreads();

        // S = (Q * scale) @ K^T, 64x64, 4x4 per thread.
        float s[4][4];
#pragma unroll
        for (int i = 0; i < 4; i++)
#pragma unroll
            for (int j = 0; j < 4; j++) s[i][j] = 0.f;

#pragma unroll
        for (int d = 0; d < 64; d++) {
            float4 a  = *(const float4*)&Qt[d * 68 + ty * 4];
            float4 bk = *(const float4*)&Kt[d * 68 + tx * 4];
            float av[4] = {a.x, a.y, a.z, a.w};
            float bv[4] = {bk.x, bk.y, bk.z, bk.w};
#pragma unroll
            for (int i = 0; i < 4; i++)
#pragma unroll
                for (int j = 0; j < 4; j++)
                    s[i][j] = fmaf(av[i], bv[j], s[i][j]);
        }

        // Online softmax (row reductions across the 16 lanes sharing ty).
#pragma unroll
        for (int i = 0; i < 4; i++) {
            float mx = fmaxf(fmaxf(s[i][0], s[i][1]), fmaxf(s[i][2], s[i][3]));
#pragma unroll
            for (int off = 8; off > 0; off >>= 1)
                mx = fmaxf(mx, __shfl_xor_sync(0xffffffffu, mx, off, 16));
            float mn   = fmaxf(mrow[i], mx);
            float corr = __expf(mrow[i] - mn);
            mrow[i] = mn;
            float rs = 0.f;
#pragma unroll
            for (int j = 0; j < 4; j++) {
                s[i][j] = __expf(s[i][j] - mn);
                rs += s[i][j];
            }
#pragma unroll
            for (int off = 8; off > 0; off >>= 1)
                rs += __shfl_xor_sync(0xffffffffu, rs, off, 16);
            lsum[i] = lsum[i] * corr + rs;
#pragma unroll
            for (int j = 0; j < 4; j++) accO[i][j] *= corr;
        }

        // Stage P transposed: Ps[k][q].
#pragma unroll
        for (int i = 0; i < 4; i++)
#pragma unroll
            for (int j = 0; j < 4; j++)
                Ps[(tx * 4 + j) * 65 + ty * 4 + i] = s[i][j];
        __syncthreads();

        // O += P @ V
#pragma unroll
        for (int k = 0; k < 64; k++) {
            float4 vb = *(const float4*)&Vs[k * 68 + tx * 4];
#pragma unroll
            for (int i = 0; i < 4; i++) {
                float pv = Ps[k * 65 + ty * 4 + i];
                accO[i][0] = fmaf(pv, vb.x, accO[i][0]);
                accO[i][1] = fmaf(pv, vb.y, accO[i][1]);
                accO[i][2] = fmaf(pv, vb.z, accO[i][2]);
                accO[i][3] = fmaf(pv, vb.w, accO[i][3]);
            }
        }
        __syncthreads();
    }

    // Epilogue: normalize and write to (B, N, D) layout.
#pragma unroll
    for (int i = 0; i < 4; i++) {
        float inv = 1.f / lsum[i];
        int n = q0 + ty * 4 + i;
        float* op = g_ao + (size_t)(b * N_ + n) * D_ + h * HD_ + tx * 4;
        op[0] = accO[i][0] * inv;
        op[1] = accO[i][1] * inv;
        op[2] = accO[i][2] * inv;
        op[3] = accO[i][3] * inv;
    }
}

// ---------------------------------------------------------------------------
extern "C" void kernel_launch(void* const* d_in, const int* in_sizes, int n_in,
                              void* d_out, int out_size)
{
    const float* x     = (const float*)d_in[0];  // (B, N, D)
    const float* pe    = (const float*)d_in[1];  // (N, HD)
    const float* Wqkv  = (const float*)d_in[2];  // (3D, D)
    const float* Wproj = (const float*)d_in[3];  // (D, D)
    const float* bproj = (const float*)d_in[4];  // (D,)
    float* out = (float*)d_out;

    float* qkv;
    float* ao;
    cudaGetSymbolAddress((void**)&qkv, g_qkv);
    cudaGetSymbolAddress((void**)&ao, g_ao);

    const int M = B_ * N_;  // 4096

    // 1) QKV projection: (4096, 768) @ (2304, 768)^T -> (4096, 2304)
    {
        dim3 grid(QKVSTRIDE / 64, M / 64);
        gemm_nt_kernel<false, true><<<grid, 256>>>(x, Wqkv, nullptr, qkv,
                                                   M, QKVSTRIDE, D_);
    }

    // 2) RoPE in-place on q, k
    {
        int total = B_ * N_ * 2 * H_ * 32;
        rope_kernel<<<(total + 255) / 256, 256>>>(pe);
    }

    // 3) Attention
    {
        const int smem = (68 * 3 * 64 + 65 * 64) * (int)sizeof(float); // 68864
        cudaFuncSetAttribute(attn_kernel,
                             cudaFuncAttributeMaxDynamicSharedMemorySize, smem);
        dim3 grid(N_ / 64, B_ * H_);
        attn_kernel<<<grid, 256, smem>>>();
    }

    // 4) Output projection: (4096, 768) @ (768, 768)^T + bias -> d_out
    {
        dim3 grid(D_ / 64, M / 64);
        gemm_nt_kernel<true, false><<<grid, 256>>>(ao, Wproj, bproj, out,
                                                   M, D_, D_);
    }
}

// round 3
// speedup vs baseline: 1.3501x; 1.3501x over previous
#include <cuda_runtime.h>
#include <cuda_bf16.h>
#include <cstdint>
#include <math.h>

#define B_ 2
#define N_ 2048
#define D_ 768
#define H_ 12
#define HD_ 64
#define QKVSTRIDE (3 * D_)   // 2304

// ---------------- scratch (allocation-free) ----------------
__device__ float g_qkv[(size_t)B_ * N_ * 3 * D_];   // (B, N, 3*D) fp32
__device__ float g_ao [(size_t)B_ * N_ * D_];       // (B, N, D)   fp32
// bf16 hi/lo splits
__device__ __nv_bfloat16 g_xh[(size_t)B_ * N_ * D_];
__device__ __nv_bfloat16 g_xl[(size_t)B_ * N_ * D_];
__device__ __nv_bfloat16 g_wqh[(size_t)QKVSTRIDE * D_];
__device__ __nv_bfloat16 g_wql[(size_t)QKVSTRIDE * D_];
__device__ __nv_bfloat16 g_aoh[(size_t)B_ * N_ * D_];
__device__ __nv_bfloat16 g_aol[(size_t)B_ * N_ * D_];
__device__ __nv_bfloat16 g_wph[(size_t)D_ * D_];
__device__ __nv_bfloat16 g_wpl[(size_t)D_ * D_];

// ---------------- mma.sync / ldmatrix helpers (valid on plain sm_103) ------
__device__ __forceinline__ void ldsm_x4(uint32_t* r, const void* p) {
    uint32_t a = (uint32_t)__cvta_generic_to_shared(p);
    asm volatile("ldmatrix.sync.aligned.m8n8.x4.shared.b16 {%0,%1,%2,%3}, [%4];"
                 : "=r"(r[0]), "=r"(r[1]), "=r"(r[2]), "=r"(r[3]) : "r"(a));
}
__device__ __forceinline__ void ldsm_x2(uint32_t* r, const void* p) {
    uint32_t a = (uint32_t)__cvta_generic_to_shared(p);
    asm volatile("ldmatrix.sync.aligned.m8n8.x2.shared.b16 {%0,%1}, [%2];"
                 : "=r"(r[0]), "=r"(r[1]) : "r"(a));
}
__device__ __forceinline__ void mma16816(float* c, const uint32_t* a, const uint32_t* b) {
    asm volatile(
        "mma.sync.aligned.m16n8k16.row.col.f32.bf16.bf16.f32 "
        "{%0,%1,%2,%3}, {%4,%5,%6,%7}, {%8,%9}, {%0,%1,%2,%3};"
        : "+f"(c[0]), "+f"(c[1]), "+f"(c[2]), "+f"(c[3])
        : "r"(a[0]), "r"(a[1]), "r"(a[2]), "r"(a[3]), "r"(b[0]), "r"(b[1]));
}

// ---------------------------------------------------------------------------
// split fp32 -> bf16 hi + bf16 lo (vectorized float4)
// ---------------------------------------------------------------------------
__global__ void split_bf16_kernel(const float4* __restrict__ in,
                                  uint2* __restrict__ hi, uint2* __restrict__ lo, int n4)
{
    int i = blockIdx.x * blockDim.x + threadIdx.x;
    if (i >= n4) return;
    float4 v = in[i];
    __nv_bfloat16 hx = __float2bfloat16(v.x), hy = __float2bfloat16(v.y);
    __nv_bfloat16 hz = __float2bfloat16(v.z), hw = __float2bfloat16(v.w);
    __nv_bfloat16 lx = __float2bfloat16(v.x - __bfloat162float(hx));
    __nv_bfloat16 ly = __float2bfloat16(v.y - __bfloat162float(hy));
    __nv_bfloat16 lz = __float2bfloat16(v.z - __bfloat162float(hz));
    __nv_bfloat16 lw = __float2bfloat16(v.w - __bfloat162float(hw));
    __nv_bfloat162 h01; h01.x = hx; h01.y = hy;
    __nv_bfloat162 h23; h23.x = hz; h23.y = hw;
    __nv_bfloat162 l01; l01.x = lx; l01.y = ly;
    __nv_bfloat162 l23; l23.x = lz; l23.y = lw;
    uint2 ho, loo;
    ho.x  = *reinterpret_cast<uint32_t*>(&h01); ho.y  = *reinterpret_cast<uint32_t*>(&h23);
    loo.x = *reinterpret_cast<uint32_t*>(&l01); loo.y = *reinterpret_cast<uint32_t*>(&l23);
    hi[i] = ho; lo[i] = loo;
}

// ---------------------------------------------------------------------------
// HMMA GEMM: C[M,Nc] = (Ah+Al)[M,K] @ (Wh+Wl)[Nc,K]^T (+bias)
// CTA = 128x128 tile, BK=32. 8 warps in 2x4; each warp 64x32 via m16n8k16.
// hi/lo split: 3 MMAs per tile per K16 step.
// Smem row stride = 40 bf16 (80B) -> 8 consecutive-row ldmatrix addresses hit
// 8 distinct 16B slots mod 128B (conflict-free).
// ---------------------------------------------------------------------------
#define SSTR 40

template <bool BIAS>
__global__ __launch_bounds__(256) void gemm_mma_kernel(
    const __nv_bfloat16* __restrict__ Ah, const __nv_bfloat16* __restrict__ Al,
    const __nv_bfloat16* __restrict__ Wh, const __nv_bfloat16* __restrict__ Wl,
    const float* __restrict__ bias, float* __restrict__ C,
    int M, int Nc, int K)
{
    __shared__ __nv_bfloat16 sAh[128 * SSTR], sAl[128 * SSTR];
    __shared__ __nv_bfloat16 sWh[128 * SSTR], sWl[128 * SSTR];

    const int tid  = threadIdx.x;
    const int lane = tid & 31;
    const int wid  = tid >> 5;
    const int wm   = wid & 1;    // 0..1 -> 64 rows each
    const int wn   = wid >> 1;   // 0..3 -> 32 cols each
    const int m0   = blockIdx.y * 128;
    const int n0   = blockIdx.x * 128;

    float acc[4][4][4];
#pragma unroll
    for (int mt = 0; mt < 4; mt++)
#pragma unroll
        for (int nt = 0; nt < 4; nt++)
#pragma unroll
            for (int e = 0; e < 4; e++) acc[mt][nt][e] = 0.f;

    for (int kk = 0; kk < K; kk += 32) {
        // load 128 rows x 32 bf16 per array (512 uint4 each)
        for (int f = tid; f < 512; f += 256) {
            int row = f >> 2;
            int ch  = (f & 3) * 8;     // element col
            size_t ga = (size_t)(m0 + row) * K + kk + ch;
            size_t gw = (size_t)(n0 + row) * K + kk + ch;
            *(uint4*)&sAh[row * SSTR + ch] = *(const uint4*)(Ah + ga);
            *(uint4*)&sAl[row * SSTR + ch] = *(const uint4*)(Al + ga);
            *(uint4*)&sWh[row * SSTR + ch] = *(const uint4*)(Wh + gw);
            *(uint4*)&sWl[row * SSTR + ch] = *(const uint4*)(Wl + gw);
        }
        __syncthreads();

#pragma unroll
        for (int ks = 0; ks < 2; ks++) {
            uint32_t ah[4][4], al[4][4], bh[4][2], bl[4][2];
            const int acol = ks * 16 + (lane >> 4) * 8;        // A frag col
            const int bcol = ks * 16 + ((lane >> 3) & 1) * 8;  // B frag col
#pragma unroll
            for (int mt = 0; mt < 4; mt++) {
                int r = wm * 64 + mt * 16 + (lane & 15);
                ldsm_x4(ah[mt], &sAh[r * SSTR + acol]);
                ldsm_x4(al[mt], &sAl[r * SSTR + acol]);
            }
#pragma unroll
            for (int nt = 0; nt < 4; nt++) {
                int r = wn * 32 + nt * 8 + (lane & 7);
                ldsm_x2(bh[nt], &sWh[r * SSTR + bcol]);
                ldsm_x2(bl[nt], &sWl[r * SSTR + bcol]);
            }
#pragma unroll
            for (int mt = 0; mt < 4; mt++)
#pragma unroll
                for (int nt = 0; nt < 4; nt++) {
                    mma16816(acc[mt][nt], ah[mt], bh[nt]);
                    mma16816(acc[mt][nt], ah[mt], bl[nt]);
                    mma16816(acc[mt][nt], al[mt], bh[nt]);
                }
        }
        __syncthreads();
    }

    // Epilogue: direct float2 stores from accumulator fragments.
#pragma unroll
    for (int mt = 0; mt < 4; mt++) {
        int m = m0 + wm * 64 + mt * 16 + (lane >> 2);
#pragma unroll
        for (int nt = 0; nt < 4; nt++) {
            int n = n0 + wn * 32 + nt * 8 + (lane & 3) * 2;
            float bx = 0.f, by = 0.f;
            if (BIAS) { float2 bb = *(const float2*)&bias[n]; bx = bb.x; by = bb.y; }
            float2 v0 = {acc[mt][nt][0] + bx, acc[mt][nt][1] + by};
            float2 v1 = {acc[mt][nt][2] + bx, acc[mt][nt][3] + by};
            *(float2*)&C[(size_t)m * Nc + n]       = v0;
            *(float2*)&C[(size_t)(m + 8) * Nc + n] = v1;
        }
    }
}

// ---------------------------------------------------------------------------
// RoPE in-place on q,k slices of g_qkv
// ---------------------------------------------------------------------------
__global__ void rope_kernel(const float* __restrict__ pe)
{
    int idx = blockIdx.x * blockDim.x + threadIdx.x;
    const int total = B_ * N_ * 2 * H_ * 32;
    if (idx >= total) return;
    int d = idx & 31;  int r = idx >> 5;
    int h = r % H_;    r /= H_;
    int c = r & 1;     r >>= 1;
    int n = r % N_;    int b = r / N_;

    float* p = g_qkv + (size_t)(b * N_ + n) * QKVSTRIDE + c * D_ + h * HD_;
    float x1 = p[d];
    float x2 = p[d + 32];
    float s1, c1, s2, c2;
    sincosf(pe[n * HD_ + d],      &s1, &c1);
    sincosf(pe[n * HD_ + d + 32], &s2, &c2);
    p[d]      = x1 * c1 - x2 * s1;
    p[d + 32] = x2 * c2 + x1 * s2;
}

// ---------------------------------------------------------------------------
// Flash-style fp32 attention (unchanged, proven)
// ---------------------------------------------------------------------------
__global__ __launch_bounds__(256) void attn_kernel()
{
    extern __shared__ float smf[];
    float* Qt = smf;
    float* Kt = Qt + 64 * 68;
    float* Vs = Kt + 64 * 68;
    float* Ps = Vs + 64 * 68;

    const int t  = threadIdx.x;
    const int tx = t & 15;
    const int ty = t >> 4;
    const int bh = blockIdx.y;
    const int b  = bh / H_;
    const int h  = bh % H_;
    const int q0 = blockIdx.x * 64;

    const float* qbase = g_qkv + (size_t)b * N_ * QKVSTRIDE + h * HD_;
    const float* kbase = qbase + D_;
    const float* vbase = qbase + 2 * D_;

    const int lrow = t >> 4;
    const int d4   = (t & 15) * 4;

#pragma unroll
    for (int it = 0; it < 4; it++) {
        int row = lrow + it * 16;
        float4 qv = *(const float4*)(qbase + (size_t)(q0 + row) * QKVSTRIDE + d4);
        Qt[(d4 + 0) * 68 + row] = qv.x * 0.125f;
        Qt[(d4 + 1) * 68 + row] = qv.y * 0.125f;
        Qt[(d4 + 2) * 68 + row] = qv.z * 0.125f;
        Qt[(d4 + 3) * 68 + row] = qv.w * 0.125f;
    }

    float accO[4][4];
    float mrow[4], lsum[4];
#pragma unroll
    for (int i = 0; i < 4; i++) {
        mrow[i] = -1e30f; lsum[i] = 0.f;
#pragma unroll
        for (int j = 0; j < 4; j++) accO[i][j] = 0.f;
    }

    for (int kt = 0; kt < N_ / 64; kt++) {
        const int k0 = kt * 64;
#pragma unroll
        for (int it = 0; it < 4; it++) {
            int row = lrow + it * 16;
            float4 kv = *(const float4*)(kbase + (size_t)(k0 + row) * QKVSTRIDE + d4);
            Kt[(d4 + 0) * 68 + row] = kv.x;
            Kt[(d4 + 1) * 68 + row] = kv.y;
            Kt[(d4 + 2) * 68 + row] = kv.z;
            Kt[(d4 + 3) * 68 + row] = kv.w;
            float4 vv = *(const float4*)(vbase + (size_t)(k0 + row) * QKVSTRIDE + d4);
            *(float4*)&Vs[row * 68 + d4] = vv;
        }
        __syncthreads();

        float s[4][4];
#pragma unroll
        for (int i = 0; i < 4; i++)
#pragma unroll
            for (int j = 0; j < 4; j++) s[i][j] = 0.f;

#pragma unroll
        for (int d = 0; d < 64; d++) {
            float4 a  = *(const float4*)&Qt[d * 68 + ty * 4];
            float4 bk = *(const float4*)&Kt[d * 68 + tx * 4];
            float av[4] = {a.x, a.y, a.z, a.w};
            float bv[4] = {bk.x, bk.y, bk.z, bk.w};
#pragma unroll
            for (int i = 0; i < 4; i++)
#pragma unroll
                for (int j = 0; j < 4; j++)
                    s[i][j] = fmaf(av[i], bv[j], s[i][j]);
        }

#pragma unroll
        for (int i = 0; i < 4; i++) {
            float mx = fmaxf(fmaxf(s[i][0], s[i][1]), fmaxf(s[i][2], s[i][3]));
#pragma unroll
            for (int off = 8; off > 0; off >>= 1)
                mx = fmaxf(mx, __shfl_xor_sync(0xffffffffu, mx, off, 16));
            float mn   = fmaxf(mrow[i], mx);
            float corr = __expf(mrow[i] - mn);
            mrow[i] = mn;
            float rs = 0.f;
#pragma unroll
            for (int j = 0; j < 4; j++) {
                s[i][j] = __expf(s[i][j] - mn);
                rs += s[i][j];
            }
#pragma unroll
            for (int off = 8; off > 0; off >>= 1)
                rs += __shfl_xor_sync(0xffffffffu, rs, off, 16);
            lsum[i] = lsum[i] * corr + rs;
#pragma unroll
            for (int j = 0; j < 4; j++) accO[i][j] *= corr;
        }

#pragma unroll
        for (int i = 0; i < 4; i++)
#pragma unroll
            for (int j = 0; j < 4; j++)
                Ps[(tx * 4 + j) * 65 + ty * 4 + i] = s[i][j];
        __syncthreads();

#pragma unroll
        for (int k = 0; k < 64; k++) {
            float4 vb = *(const float4*)&Vs[k * 68 + tx * 4];
#pragma unroll
            for (int i = 0; i < 4; i++) {
                float pv = Ps[k * 65 + ty * 4 + i];
                accO[i][0] = fmaf(pv, vb.x, accO[i][0]);
                accO[i][1] = fmaf(pv, vb.y, accO[i][1]);
                accO[i][2] = fmaf(pv, vb.z, accO[i][2]);
                accO[i][3] = fmaf(pv, vb.w, accO[i][3]);
            }
        }
        __syncthreads();
    }

#pragma unroll
    for (int i = 0; i < 4; i++) {
        float inv = 1.f / lsum[i];
        int n = q0 + ty * 4 + i;
        float* op = g_ao + (size_t)(b * N_ + n) * D_ + h * HD_ + tx * 4;
        op[0] = accO[i][0] * inv;
        op[1] = accO[i][1] * inv;
        op[2] = accO[i][2] * inv;
        op[3] = accO[i][3] * inv;
    }
}

// ---------------------------------------------------------------------------
extern "C" void kernel_launch(void* const* d_in, const int* in_sizes, int n_in,
                              void* d_out, int out_size)
{
    const float* x     = (const float*)d_in[0];
    const float* pe    = (const float*)d_in[1];
    const float* Wqkv  = (const float*)d_in[2];
    const float* Wproj = (const float*)d_in[3];
    const float* bproj = (const float*)d_in[4];
    float* out = (float*)d_out;

    float *qkv, *ao;
    __nv_bfloat16 *xh, *xl, *wqh, *wql, *aoh, *aol, *wph, *wpl;
    cudaGetSymbolAddress((void**)&qkv, g_qkv);
    cudaGetSymbolAddress((void**)&ao,  g_ao);
    cudaGetSymbolAddress((void**)&xh,  g_xh);
    cudaGetSymbolAddress((void**)&xl,  g_xl);
    cudaGetSymbolAddress((void**)&wqh, g_wqh);
    cudaGetSymbolAddress((void**)&wql, g_wql);
    cudaGetSymbolAddress((void**)&aoh, g_aoh);
    cudaGetSymbolAddress((void**)&aol, g_aol);
    cudaGetSymbolAddress((void**)&wph, g_wph);
    cudaGetSymbolAddress((void**)&wpl, g_wpl);

    const int M = B_ * N_;           // 4096

    // splits for QKV GEMM
    {
        int n4 = (M * D_) / 4;
        split_bf16_kernel<<<(n4 + 255) / 256, 256>>>((const float4*)x, (uint2*)xh, (uint2*)xl, n4);
        int w4 = (QKVSTRIDE * D_) / 4;
        split_bf16_kernel<<<(w4 + 255) / 256, 256>>>((const float4*)Wqkv, (uint2*)wqh, (uint2*)wql, w4);
    }
    // 1) QKV projection
    {
        dim3 grid(QKVSTRIDE / 128, M / 128);
        gemm_mma_kernel<false><<<grid, 256>>>(xh, xl, wqh, wql, nullptr, qkv,
                                              M, QKVSTRIDE, D_);
    }
    // 2) RoPE
    {
        int total = B_ * N_ * 2 * H_ * 32;
        rope_kernel<<<(total + 255) / 256, 256>>>(pe);
    }
    // 3) Attention
    {
        const int smem = (68 * 3 * 64 + 65 * 64) * (int)sizeof(float);
        cudaFuncSetAttribute(attn_kernel,
                             cudaFuncAttributeMaxDynamicSharedMemorySize, smem);
        dim3 grid(N_ / 64, B_ * H_);
        attn_kernel<<<grid, 256, smem>>>();
    }
    // splits for out projection
    {
        int n4 = (M * D_) / 4;
        split_bf16_kernel<<<(n4 + 255) / 256, 256>>>((const float4*)ao, (uint2*)aoh, (uint2*)aol, n4);
        int w4 = (D_ * D_) / 4;
        split_bf16_kernel<<<(w4 + 255) / 256, 256>>>((const float4*)Wproj, (uint2*)wph, (uint2*)wpl, w4);
    }
    // 4) output projection
    {
        dim3 grid(D_ / 128, M / 128);
        gemm_mma_kernel<true><<<grid, 256>>>(aoh, aol, wph, wpl, bproj, out,
                                             M, D_, D_);
    }
}

// round 4
// speedup vs baseline: 2.4812x; 1.8378x over previous
#include <cuda_runtime.h>
#include <cuda_bf16.h>
#include <cstdint>
#include <math.h>

#define B_ 2
#define N_ 2048
#define D_ 768
#define H_ 12
#define HD_ 64
#define QKVSTRIDE (3 * D_)   // 2304

// ---------------- scratch (allocation-free) ----------------
__device__ float g_qkv[(size_t)B_ * N_ * 3 * D_];   // (B, N, 3*D) fp32
__device__ float g_ao [(size_t)B_ * N_ * D_];       // (B, N, D)   fp32
__device__ __nv_bfloat16 g_xh[(size_t)B_ * N_ * D_];
__device__ __nv_bfloat16 g_xl[(size_t)B_ * N_ * D_];
__device__ __nv_bfloat16 g_wqh[(size_t)QKVSTRIDE * D_];
__device__ __nv_bfloat16 g_wql[(size_t)QKVSTRIDE * D_];
__device__ __nv_bfloat16 g_aoh[(size_t)B_ * N_ * D_];
__device__ __nv_bfloat16 g_aol[(size_t)B_ * N_ * D_];
__device__ __nv_bfloat16 g_wph[(size_t)D_ * D_];
__device__ __nv_bfloat16 g_wpl[(size_t)D_ * D_];

// ---------------- mma.sync / ldmatrix helpers ----------------
__device__ __forceinline__ void ldsm_x4(uint32_t* r, const void* p) {
    uint32_t a = (uint32_t)__cvta_generic_to_shared(p);
    asm volatile("ldmatrix.sync.aligned.m8n8.x4.shared.b16 {%0,%1,%2,%3}, [%4];"
                 : "=r"(r[0]), "=r"(r[1]), "=r"(r[2]), "=r"(r[3]) : "r"(a));
}
__device__ __forceinline__ void ldsm_x2(uint32_t* r, const void* p) {
    uint32_t a = (uint32_t)__cvta_generic_to_shared(p);
    asm volatile("ldmatrix.sync.aligned.m8n8.x2.shared.b16 {%0,%1}, [%2];"
                 : "=r"(r[0]), "=r"(r[1]) : "r"(a));
}
__device__ __forceinline__ void mma16816(float* c, const uint32_t* a, const uint32_t* b) {
    asm volatile(
        "mma.sync.aligned.m16n8k16.row.col.f32.bf16.bf16.f32 "
        "{%0,%1,%2,%3}, {%4,%5,%6,%7}, {%8,%9}, {%0,%1,%2,%3};"
        : "+f"(c[0]), "+f"(c[1]), "+f"(c[2]), "+f"(c[3])
        : "r"(a[0]), "r"(a[1]), "r"(a[2]), "r"(a[3]), "r"(b[0]), "r"(b[1]));
}
__device__ __forceinline__ void split2(float a, float b, uint32_t& h, uint32_t& l) {
    __nv_bfloat16 ha = __float2bfloat16(a), hb = __float2bfloat16(b);
    __nv_bfloat16 la = __float2bfloat16(a - __bfloat162float(ha));
    __nv_bfloat16 lb = __float2bfloat16(b - __bfloat162float(hb));
    h = (uint32_t)*(uint16_t*)&ha | ((uint32_t)*(uint16_t*)&hb << 16);
    l = (uint32_t)*(uint16_t*)&la | ((uint32_t)*(uint16_t*)&lb << 16);
}

// ---------------------------------------------------------------------------
// split fp32 -> bf16 hi + bf16 lo (vectorized float4)
// ---------------------------------------------------------------------------
__global__ void split_bf16_kernel(const float4* __restrict__ in,
                                  uint2* __restrict__ hi, uint2* __restrict__ lo, int n4)
{
    int i = blockIdx.x * blockDim.x + threadIdx.x;
    if (i >= n4) return;
    float4 v = in[i];
    uint2 ho, loo;
    split2(v.x, v.y, ho.x, loo.x);
    split2(v.z, v.w, ho.y, loo.y);
    hi[i] = ho; lo[i] = loo;
}

// ---------------------------------------------------------------------------
// HMMA GEMM (unchanged from R3, proven): C = (Ah+Al) @ (Wh+Wl)^T (+bias)
// ---------------------------------------------------------------------------
#define SSTR 40

template <bool BIAS>
__global__ __launch_bounds__(256) void gemm_mma_kernel(
    const __nv_bfloat16* __restrict__ Ah, const __nv_bfloat16* __restrict__ Al,
    const __nv_bfloat16* __restrict__ Wh, const __nv_bfloat16* __restrict__ Wl,
    const float* __restrict__ bias, float* __restrict__ C,
    int M, int Nc, int K)
{
    __shared__ __nv_bfloat16 sAh[128 * SSTR], sAl[128 * SSTR];
    __shared__ __nv_bfloat16 sWh[128 * SSTR], sWl[128 * SSTR];

    const int tid  = threadIdx.x;
    const int lane = tid & 31;
    const int wid  = tid >> 5;
    const int wm   = wid & 1;
    const int wn   = wid >> 1;
    const int m0   = blockIdx.y * 128;
    const int n0   = blockIdx.x * 128;

    float acc[4][4][4];
#pragma unroll
    for (int mt = 0; mt < 4; mt++)
#pragma unroll
        for (int nt = 0; nt < 4; nt++)
#pragma unroll
            for (int e = 0; e < 4; e++) acc[mt][nt][e] = 0.f;

    for (int kk = 0; kk < K; kk += 32) {
        for (int f = tid; f < 512; f += 256) {
            int row = f >> 2;
            int ch  = (f & 3) * 8;
            size_t ga = (size_t)(m0 + row) * K + kk + ch;
            size_t gw = (size_t)(n0 + row) * K + kk + ch;
            *(uint4*)&sAh[row * SSTR + ch] = *(const uint4*)(Ah + ga);
            *(uint4*)&sAl[row * SSTR + ch] = *(const uint4*)(Al + ga);
            *(uint4*)&sWh[row * SSTR + ch] = *(const uint4*)(Wh + gw);
            *(uint4*)&sWl[row * SSTR + ch] = *(const uint4*)(Wl + gw);
        }
        __syncthreads();

#pragma unroll
        for (int ks = 0; ks < 2; ks++) {
            uint32_t ah[4][4], al[4][4], bh[4][2], bl[4][2];
            const int acol = ks * 16 + (lane >> 4) * 8;
            const int bcol = ks * 16 + ((lane >> 3) & 1) * 8;
#pragma unroll
            for (int mt = 0; mt < 4; mt++) {
                int r = wm * 64 + mt * 16 + (lane & 15);
                ldsm_x4(ah[mt], &sAh[r * SSTR + acol]);
                ldsm_x4(al[mt], &sAl[r * SSTR + acol]);
            }
#pragma unroll
            for (int nt = 0; nt < 4; nt++) {
                int r = wn * 32 + nt * 8 + (lane & 7);
                ldsm_x2(bh[nt], &sWh[r * SSTR + bcol]);
                ldsm_x2(bl[nt], &sWl[r * SSTR + bcol]);
            }
#pragma unroll
            for (int mt = 0; mt < 4; mt++)
#pragma unroll
                for (int nt = 0; nt < 4; nt++) {
                    mma16816(acc[mt][nt], ah[mt], bh[nt]);
                    mma16816(acc[mt][nt], ah[mt], bl[nt]);
                    mma16816(acc[mt][nt], al[mt], bh[nt]);
                }
        }
        __syncthreads();
    }

#pragma unroll
    for (int mt = 0; mt < 4; mt++) {
        int m = m0 + wm * 64 + mt * 16 + (lane >> 2);
#pragma unroll
        for (int nt = 0; nt < 4; nt++) {
            int n = n0 + wn * 32 + nt * 8 + (lane & 3) * 2;
            float bx = 0.f, by = 0.f;
            if (BIAS) { float2 bb = *(const float2*)&bias[n]; bx = bb.x; by = bb.y; }
            float2 v0 = {acc[mt][nt][0] + bx, acc[mt][nt][1] + by};
            float2 v1 = {acc[mt][nt][2] + bx, acc[mt][nt][3] + by};
            *(float2*)&C[(size_t)m * Nc + n]       = v0;
            *(float2*)&C[(size_t)(m + 8) * Nc + n] = v1;
        }
    }
}

// ---------------------------------------------------------------------------
// RoPE in-place on q,k slices of g_qkv
// ---------------------------------------------------------------------------
__global__ void rope_kernel(const float* __restrict__ pe)
{
    int idx = blockIdx.x * blockDim.x + threadIdx.x;
    const int total = B_ * N_ * 2 * H_ * 32;
    if (idx >= total) return;
    int d = idx & 31;  int r = idx >> 5;
    int h = r % H_;    r /= H_;
    int c = r & 1;     r >>= 1;
    int n = r % N_;    int b = r / N_;

    float* p = g_qkv + (size_t)(b * N_ + n) * QKVSTRIDE + c * D_ + h * HD_;
    float x1 = p[d];
    float x2 = p[d + 32];
    float s1, c1, s2, c2;
    sincosf(pe[n * HD_ + d],      &s1, &c1);
    sincosf(pe[n * HD_ + d + 32], &s2, &c2);
    p[d]      = x1 * c1 - x2 * s1;
    p[d + 32] = x2 * c2 + x1 * s2;
}

// ---------------------------------------------------------------------------
// Tensor-core flash attention. CTA = 128 queries of one (b,h); 8 warps,
// warp w owns q rows [16w, 16w+16). 16 key tiles of 128.
// S and PV both via m16n8k16 bf16 hi/lo (3 MMAs each); P reused in registers.
// Smem (bf16): Qh/Ql[128][72], Kh/Kl[128][72], Vth/Vtl[64][136].
// ---------------------------------------------------------------------------
#define QKS 72
#define VTS 136

__global__ __launch_bounds__(256, 1) void attn_mma_kernel()
{
    extern __shared__ __nv_bfloat16 smb[];
    __nv_bfloat16* sQh = smb;
    __nv_bfloat16* sQl = sQh + 128 * QKS;
    __nv_bfloat16* sKh = sQl + 128 * QKS;
    __nv_bfloat16* sKl = sKh + 128 * QKS;
    __nv_bfloat16* sVh = sKl + 128 * QKS;   // transposed: [d][key]
    __nv_bfloat16* sVl = sVh + 64 * VTS;

    const int tid  = threadIdx.x;
    const int lane = tid & 31;
    const int wid  = tid >> 5;
    const int w16  = wid * 16;
    const int b    = blockIdx.y / H_;
    const int h    = blockIdx.y % H_;
    const int q0   = blockIdx.x * 128;

    const float* qbase = g_qkv + (size_t)b * N_ * QKVSTRIDE + h * HD_;
    const float* kbase = qbase + D_;
    const float* vbase = qbase + 2 * D_;

    // ---- load Q tile (scaled by 1/sqrt(HD)), split to hi/lo ----
    for (int f = tid; f < 2048; f += 256) {
        int row = f >> 4;
        int c4  = (f & 15) * 4;
        float4 v = *(const float4*)(qbase + (size_t)(q0 + row) * QKVSTRIDE + c4);
        v.x *= 0.125f; v.y *= 0.125f; v.z *= 0.125f; v.w *= 0.125f;
        uint32_t h0, l0, h1, l1;
        split2(v.x, v.y, h0, l0);
        split2(v.z, v.w, h1, l1);
        *(uint32_t*)&sQh[row * QKS + c4]     = h0;
        *(uint32_t*)&sQh[row * QKS + c4 + 2] = h1;
        *(uint32_t*)&sQl[row * QKS + c4]     = l0;
        *(uint32_t*)&sQl[row * QKS + c4 + 2] = l1;
    }

    float oacc[8][4];
#pragma unroll
    for (int ob = 0; ob < 8; ob++)
#pragma unroll
        for (int e = 0; e < 4; e++) oacc[ob][e] = 0.f;
    float m0 = -1e30f, m1 = -1e30f, l0 = 0.f, l1 = 0.f;

    for (int kt = 0; kt < N_ / 128; kt++) {
        const int k0 = kt * 128;
        // ---- load K (row-major) and V (transposed) tiles, split hi/lo ----
        for (int f = tid; f < 2048; f += 256) {
            int row = f >> 4;
            int c4  = (f & 15) * 4;
            float4 kv = *(const float4*)(kbase + (size_t)(k0 + row) * QKVSTRIDE + c4);
            uint32_t h0v, l0v, h1v, l1v;
            split2(kv.x, kv.y, h0v, l0v);
            split2(kv.z, kv.w, h1v, l1v);
            *(uint32_t*)&sKh[row * QKS + c4]     = h0v;
            *(uint32_t*)&sKh[row * QKS + c4 + 2] = h1v;
            *(uint32_t*)&sKl[row * QKS + c4]     = l0v;
            *(uint32_t*)&sKl[row * QKS + c4 + 2] = l1v;

            float4 vv = *(const float4*)(vbase + (size_t)(k0 + row) * QKVSTRIDE + c4);
            float ve[4] = {vv.x, vv.y, vv.z, vv.w};
#pragma unroll
            for (int j = 0; j < 4; j++) {
                __nv_bfloat16 hh = __float2bfloat16(ve[j]);
                __nv_bfloat16 ll = __float2bfloat16(ve[j] - __bfloat162float(hh));
                sVh[(c4 + j) * VTS + row] = hh;
                sVl[(c4 + j) * VTS + row] = ll;
            }
        }
        __syncthreads();

        // ---- S = Q @ K^T (16 rows x 128 keys per warp) ----
        float sacc[16][4];
#pragma unroll
        for (int nb = 0; nb < 16; nb++)
#pragma unroll
            for (int e = 0; e < 4; e++) sacc[nb][e] = 0.f;

#pragma unroll
        for (int ks = 0; ks < 4; ks++) {
            uint32_t ah[4], al[4];
            const int acol = ks * 16 + (lane >> 4) * 8;
            ldsm_x4(ah, &sQh[(w16 + (lane & 15)) * QKS + acol]);
            ldsm_x4(al, &sQl[(w16 + (lane & 15)) * QKS + acol]);
            const int bcol = ks * 16 + ((lane >> 3) & 1) * 8;
#pragma unroll
            for (int nb = 0; nb < 16; nb++) {
                uint32_t bh[2], bl[2];
                ldsm_x2(bh, &sKh[(nb * 8 + (lane & 7)) * QKS + bcol]);
                ldsm_x2(bl, &sKl[(nb * 8 + (lane & 7)) * QKS + bcol]);
                mma16816(sacc[nb], ah, bh);
                mma16816(sacc[nb], ah, bl);
                mma16816(sacc[nb], al, bh);
            }
        }

        // ---- online softmax (rows r0 = lane/4, r1 = r0+8) ----
        float mx0 = -1e30f, mx1 = -1e30f;
#pragma unroll
        for (int nb = 0; nb < 16; nb++) {
            mx0 = fmaxf(mx0, fmaxf(sacc[nb][0], sacc[nb][1]));
            mx1 = fmaxf(mx1, fmaxf(sacc[nb][2], sacc[nb][3]));
        }
        mx0 = fmaxf(mx0, __shfl_xor_sync(0xffffffffu, mx0, 1));
        mx0 = fmaxf(mx0, __shfl_xor_sync(0xffffffffu, mx0, 2));
        mx1 = fmaxf(mx1, __shfl_xor_sync(0xffffffffu, mx1, 1));
        mx1 = fmaxf(mx1, __shfl_xor_sync(0xffffffffu, mx1, 2));

        float mn0 = fmaxf(m0, mx0);
        float mn1 = fmaxf(m1, mx1);
        float cr0 = __expf(m0 - mn0);
        float cr1 = __expf(m1 - mn1);
        m0 = mn0; m1 = mn1;

        float rs0 = 0.f, rs1 = 0.f;
#pragma unroll
        for (int nb = 0; nb < 16; nb++) {
            sacc[nb][0] = __expf(sacc[nb][0] - mn0);
            sacc[nb][1] = __expf(sacc[nb][1] - mn0);
            sacc[nb][2] = __expf(sacc[nb][2] - mn1);
            sacc[nb][3] = __expf(sacc[nb][3] - mn1);
            rs0 += sacc[nb][0] + sacc[nb][1];
            rs1 += sacc[nb][2] + sacc[nb][3];
        }
        rs0 += __shfl_xor_sync(0xffffffffu, rs0, 1);
        rs0 += __shfl_xor_sync(0xffffffffu, rs0, 2);
        rs1 += __shfl_xor_sync(0xffffffffu, rs1, 1);
        rs1 += __shfl_xor_sync(0xffffffffu, rs1, 2);
        l0 = l0 * cr0 + rs0;
        l1 = l1 * cr1 + rs1;
#pragma unroll
        for (int ob = 0; ob < 8; ob++) {
            oacc[ob][0] *= cr0; oacc[ob][1] *= cr0;
            oacc[ob][2] *= cr1; oacc[ob][3] *= cr1;
        }

        // ---- pack P into bf16 hi/lo A fragments (register reuse) ----
        uint32_t pah[8][4], pal[8][4];
#pragma unroll
        for (int kb = 0; kb < 8; kb++) {
            split2(sacc[2 * kb][0],     sacc[2 * kb][1],     pah[kb][0], pal[kb][0]);
            split2(sacc[2 * kb][2],     sacc[2 * kb][3],     pah[kb][1], pal[kb][1]);
            split2(sacc[2 * kb + 1][0], sacc[2 * kb + 1][1], pah[kb][2], pal[kb][2]);
            split2(sacc[2 * kb + 1][2], sacc[2 * kb + 1][3], pah[kb][3], pal[kb][3]);
        }

        // ---- O += P @ V ----
#pragma unroll
        for (int ob = 0; ob < 8; ob++) {
#pragma unroll
            for (int kb = 0; kb < 8; kb++) {
                const int bcol = kb * 16 + ((lane >> 3) & 1) * 8;
                uint32_t bh[2], bl[2];
                ldsm_x2(bh, &sVh[(ob * 8 + (lane & 7)) * VTS + bcol]);
                ldsm_x2(bl, &sVl[(ob * 8 + (lane & 7)) * VTS + bcol]);
                mma16816(oacc[ob], pah[kb], bh);
                mma16816(oacc[ob], pah[kb], bl);
                mma16816(oacc[ob], pal[kb], bh);
            }
        }
        __syncthreads();
    }

    // ---- epilogue: normalize, write to (B, N, D) ----
    float inv0 = 1.f / l0;
    float inv1 = 1.f / l1;
    const int r0 = q0 + w16 + (lane >> 2);
#pragma unroll
    for (int ob = 0; ob < 8; ob++) {
        int col = h * HD_ + ob * 8 + (lane & 3) * 2;
        float2 v0 = {oacc[ob][0] * inv0, oacc[ob][1] * inv0};
        float2 v1 = {oacc[ob][2] * inv1, oacc[ob][3] * inv1};
        *(float2*)&g_ao[(size_t)(b * N_ + r0) * D_ + col]     = v0;
        *(float2*)&g_ao[(size_t)(b * N_ + r0 + 8) * D_ + col] = v1;
    }
}

// ---------------------------------------------------------------------------
extern "C" void kernel_launch(void* const* d_in, const int* in_sizes, int n_in,
                              void* d_out, int out_size)
{
    const float* x     = (const float*)d_in[0];
    const float* pe    = (const float*)d_in[1];
    const float* Wqkv  = (const float*)d_in[2];
    const float* Wproj = (const float*)d_in[3];
    const float* bproj = (const float*)d_in[4];
    float* out = (float*)d_out;

    float *qkv, *ao;
    __nv_bfloat16 *xh, *xl, *wqh, *wql, *aoh, *aol, *wph, *wpl;
    cudaGetSymbolAddress((void**)&qkv, g_qkv);
    cudaGetSymbolAddress((void**)&ao,  g_ao);
    cudaGetSymbolAddress((void**)&xh,  g_xh);
    cudaGetSymbolAddress((void**)&xl,  g_xl);
    cudaGetSymbolAddress((void**)&wqh, g_wqh);
    cudaGetSymbolAddress((void**)&wql, g_wql);
    cudaGetSymbolAddress((void**)&aoh, g_aoh);
    cudaGetSymbolAddress((void**)&aol, g_aol);
    cudaGetSymbolAddress((void**)&wph, g_wph);
    cudaGetSymbolAddress((void**)&wpl, g_wpl);

    const int M = B_ * N_;           // 4096

    // splits for QKV GEMM
    {
        int n4 = (M * D_) / 4;
        split_bf16_kernel<<<(n4 + 255) / 256, 256>>>((const float4*)x, (uint2*)xh, (uint2*)xl, n4);
        int w4 = (QKVSTRIDE * D_) / 4;
        split_bf16_kernel<<<(w4 + 255) / 256, 256>>>((const float4*)Wqkv, (uint2*)wqh, (uint2*)wql, w4);
    }
    // 1) QKV projection
    {
        dim3 grid(QKVSTRIDE / 128, M / 128);
        gemm_mma_kernel<false><<<grid, 256>>>(xh, xl, wqh, wql, nullptr, qkv,
                                              M, QKVSTRIDE, D_);
    }
    // 2) RoPE
    {
        int total = B_ * N_ * 2 * H_ * 32;
        rope_kernel<<<(total + 255) / 256, 256>>>(pe);
    }
    // 3) Attention (tensor-core flash)
    {
        const int smem = (4 * 128 * QKS + 2 * 64 * VTS) * (int)sizeof(__nv_bfloat16); // 108544
        cudaFuncSetAttribute(attn_mma_kernel,
                             cudaFuncAttributeMaxDynamicSharedMemorySize, smem);
        dim3 grid(N_ / 128, B_ * H_);
        attn_mma_kernel<<<grid, 256, smem>>>();
    }
    // splits for out projection
    {
        int n4 = (M * D_) / 4;
        split_bf16_kernel<<<(n4 + 255) / 256, 256>>>((const float4*)ao, (uint2*)aoh, (uint2*)aol, n4);
        int w4 = (D_ * D_) / 4;
        split_bf16_kernel<<<(w4 + 255) / 256, 256>>>((const float4*)Wproj, (uint2*)wph, (uint2*)wpl, w4);
    }
    // 4) output projection
    {
        dim3 grid(D_ / 128, M / 128);
        gemm_mma_kernel<true><<<grid, 256>>>(aoh, aol, wph, wpl, bproj, out,
                                             M, D_, D_);
    }
}

// round 5
// speedup vs baseline: 3.1407x; 1.2658x over previous
#include <cuda_runtime.h>
#include <cuda_bf16.h>
#include <cstdint>
#include <math.h>

#define B_ 2
#define N_ 2048
#define D_ 768
#define H_ 12
#define HD_ 64
#define QKVSTRIDE (3 * D_)   // 2304
#define BH_ (B_ * H_)        // 24

// ---------------- scratch (allocation-free) ----------------
__device__ float g_qkv[(size_t)B_ * N_ * 3 * D_];   // (B, N, 3*D) fp32
__device__ float g_ao [(size_t)B_ * N_ * D_];       // (B, N, D)   fp32
__device__ __nv_bfloat16 g_xh[(size_t)B_ * N_ * D_];
__device__ __nv_bfloat16 g_xl[(size_t)B_ * N_ * D_];
__device__ __nv_bfloat16 g_wqh[(size_t)QKVSTRIDE * D_];
__device__ __nv_bfloat16 g_wql[(size_t)QKVSTRIDE * D_];
__device__ __nv_bfloat16 g_aoh[(size_t)B_ * N_ * D_];
__device__ __nv_bfloat16 g_aol[(size_t)B_ * N_ * D_];
__device__ __nv_bfloat16 g_wph[(size_t)D_ * D_];
__device__ __nv_bfloat16 g_wpl[(size_t)D_ * D_];
// prepped attention operands (bf16 hi/lo)
__device__ __nv_bfloat16 g_qh[(size_t)BH_ * N_ * HD_];  // [bh][n][d], pre-scaled+roped
__device__ __nv_bfloat16 g_ql[(size_t)BH_ * N_ * HD_];
__device__ __nv_bfloat16 g_kh[(size_t)BH_ * N_ * HD_];  // [bh][n][d], roped
__device__ __nv_bfloat16 g_kl[(size_t)BH_ * N_ * HD_];
__device__ __nv_bfloat16 g_vh[(size_t)BH_ * HD_ * N_];  // [bh][d][n] (transposed)
__device__ __nv_bfloat16 g_vl[(size_t)BH_ * HD_ * N_];

// ---------------- helpers ----------------
__device__ __forceinline__ void ldsm_x4(uint32_t* r, const void* p) {
    uint32_t a = (uint32_t)__cvta_generic_to_shared(p);
    asm volatile("ldmatrix.sync.aligned.m8n8.x4.shared.b16 {%0,%1,%2,%3}, [%4];"
                 : "=r"(r[0]), "=r"(r[1]), "=r"(r[2]), "=r"(r[3]) : "r"(a));
}
__device__ __forceinline__ void ldsm_x2(uint32_t* r, const void* p) {
    uint32_t a = (uint32_t)__cvta_generic_to_shared(p);
    asm volatile("ldmatrix.sync.aligned.m8n8.x2.shared.b16 {%0,%1}, [%2];"
                 : "=r"(r[0]), "=r"(r[1]) : "r"(a));
}
__device__ __forceinline__ void mma16816(float* c, const uint32_t* a, const uint32_t* b) {
    asm volatile(
        "mma.sync.aligned.m16n8k16.row.col.f32.bf16.bf16.f32 "
        "{%0,%1,%2,%3}, {%4,%5,%6,%7}, {%8,%9}, {%0,%1,%2,%3};"
        : "+f"(c[0]), "+f"(c[1]), "+f"(c[2]), "+f"(c[3])
        : "r"(a[0]), "r"(a[1]), "r"(a[2]), "r"(a[3]), "r"(b[0]), "r"(b[1]));
}
__device__ __forceinline__ void split2(float a, float b, uint32_t& h, uint32_t& l) {
    __nv_bfloat16 ha = __float2bfloat16(a), hb = __float2bfloat16(b);
    __nv_bfloat16 la = __float2bfloat16(a - __bfloat162float(ha));
    __nv_bfloat16 lb = __float2bfloat16(b - __bfloat162float(hb));
    h = (uint32_t)*(uint16_t*)&ha | ((uint32_t)*(uint16_t*)&hb << 16);
    l = (uint32_t)*(uint16_t*)&la | ((uint32_t)*(uint16_t*)&lb << 16);
}
__device__ __forceinline__ void cp16(void* s, const void* g) {
    uint32_t sa = (uint32_t)__cvta_generic_to_shared(s);
    asm volatile("cp.async.ca.shared.global [%0], [%1], 16;" :: "r"(sa), "l"(g));
}
#define CP_COMMIT() asm volatile("cp.async.commit_group;" ::: "memory")
#define CP_WAIT(n)  asm volatile("cp.async.wait_group %0;" :: "n"(n) : "memory")

// ---------------------------------------------------------------------------
// split fp32 -> bf16 hi + lo
// ---------------------------------------------------------------------------
__global__ void split_bf16_kernel(const float4* __restrict__ in,
                                  uint2* __restrict__ hi, uint2* __restrict__ lo, int n4)
{
    int i = blockIdx.x * blockDim.x + threadIdx.x;
    if (i >= n4) return;
    float4 v = in[i];
    uint2 ho, loo;
    split2(v.x, v.y, ho.x, loo.x);
    split2(v.z, v.w, ho.y, loo.y);
    hi[i] = ho; lo[i] = loo;
}

// ---------------------------------------------------------------------------
// HMMA GEMM with 2-stage cp.async pipeline. C = (Ah+Al) @ (Wh+Wl)^T (+bias)
// ---------------------------------------------------------------------------
#define SSTR 40
#define GEMM_ASZ (128 * SSTR)          // elems per array per stage
#define GEMM_STG (4 * GEMM_ASZ)        // elems per stage
#define GEMM_SMEM (2 * GEMM_STG * 2)   // bytes = 81920

template <bool BIAS>
__global__ __launch_bounds__(256) void gemm_mma_kernel(
    const __nv_bfloat16* __restrict__ Ah, const __nv_bfloat16* __restrict__ Al,
    const __nv_bfloat16* __restrict__ Wh, const __nv_bfloat16* __restrict__ Wl,
    const float* __restrict__ bias, float* __restrict__ C,
    int M, int Nc, int K)
{
    extern __shared__ __nv_bfloat16 gsm[];

    const int tid  = threadIdx.x;
    const int lane = tid & 31;
    const int wid  = tid >> 5;
    const int wm   = wid & 1;
    const int wn   = wid >> 1;
    const int m0   = blockIdx.y * 128;
    const int n0   = blockIdx.x * 128;

    float acc[4][4][4];
#pragma unroll
    for (int mt = 0; mt < 4; mt++)
#pragma unroll
        for (int nt = 0; nt < 4; nt++)
#pragma unroll
            for (int e = 0; e < 4; e++) acc[mt][nt][e] = 0.f;

    const int nkt = K / 32;

    auto load_stage = [&](int st, int t) {
        __nv_bfloat16* base = gsm + st * GEMM_STG;
        const int kk = t * 32;
        for (int f = tid; f < 512; f += 256) {
            int row = f >> 2;
            int ch  = (f & 3) * 8;
            size_t ga = (size_t)(m0 + row) * K + kk + ch;
            size_t gw = (size_t)(n0 + row) * K + kk + ch;
            int so = row * SSTR + ch;
            cp16(base + so,                Ah + ga);
            cp16(base + GEMM_ASZ + so,     Al + ga);
            cp16(base + 2 * GEMM_ASZ + so, Wh + gw);
            cp16(base + 3 * GEMM_ASZ + so, Wl + gw);
        }
    };

    load_stage(0, 0);
    CP_COMMIT();

    for (int t = 0; t < nkt; t++) {
        const int cur = t & 1;
        if (t + 1 < nkt) {
            load_stage(cur ^ 1, t + 1);
            CP_COMMIT();
            CP_WAIT(1);
        } else {
            CP_WAIT(0);
        }
        __syncthreads();

        const __nv_bfloat16* sAh = gsm + cur * GEMM_STG;
        const __nv_bfloat16* sAl = sAh + GEMM_ASZ;
        const __nv_bfloat16* sWh = sAh + 2 * GEMM_ASZ;
        const __nv_bfloat16* sWl = sAh + 3 * GEMM_ASZ;

#pragma unroll
        for (int ks = 0; ks < 2; ks++) {
            uint32_t ah[4][4], al[4][4], bh[4][2], bl[4][2];
            const int acol = ks * 16 + (lane >> 4) * 8;
            const int bcol = ks * 16 + ((lane >> 3) & 1) * 8;
#pragma unroll
            for (int mt = 0; mt < 4; mt++) {
                int r = wm * 64 + mt * 16 + (lane & 15);
                ldsm_x4(ah[mt], &sAh[r * SSTR + acol]);
                ldsm_x4(al[mt], &sAl[r * SSTR + acol]);
            }
#pragma unroll
            for (int nt = 0; nt < 4; nt++) {
                int r = wn * 32 + nt * 8 + (lane & 7);
                ldsm_x2(bh[nt], &sWh[r * SSTR + bcol]);
                ldsm_x2(bl[nt], &sWl[r * SSTR + bcol]);
            }
#pragma unroll
            for (int mt = 0; mt < 4; mt++)
#pragma unroll
                for (int nt = 0; nt < 4; nt++) {
                    mma16816(acc[mt][nt], ah[mt], bh[nt]);
                    mma16816(acc[mt][nt], ah[mt], bl[nt]);
                    mma16816(acc[mt][nt], al[mt], bh[nt]);
                }
        }
        __syncthreads();
    }

#pragma unroll
    for (int mt = 0; mt < 4; mt++) {
        int m = m0 + wm * 64 + mt * 16 + (lane >> 2);
#pragma unroll
        for (int nt = 0; nt < 4; nt++) {
            int n = n0 + wn * 32 + nt * 8 + (lane & 3) * 2;
            float bx = 0.f, by = 0.f;
            if (BIAS) { float2 bb = *(const float2*)&bias[n]; bx = bb.x; by = bb.y; }
            float2 v0 = {acc[mt][nt][0] + bx, acc[mt][nt][1] + by};
            float2 v1 = {acc[mt][nt][2] + bx, acc[mt][nt][3] + by};
            *(float2*)&C[(size_t)m * Nc + n]       = v0;
            *(float2*)&C[(size_t)(m + 8) * Nc + n] = v1;
        }
    }
}

// ---------------------------------------------------------------------------
// prep_qk: RoPE + (Q scale) + hi/lo split, qkv fp32 -> [bh][n][64] bf16
// ---------------------------------------------------------------------------
__global__ void prep_qk_kernel(const float* __restrict__ pe)
{
    int idx = blockIdx.x * blockDim.x + threadIdx.x;
    const int total = B_ * N_ * 2 * H_ * 32;
    if (idx >= total) return;
    int d = idx & 31;  int r = idx >> 5;
    int h = r % H_;    r /= H_;
    int c = r & 1;     r >>= 1;
    int n = r % N_;    int b = r / N_;

    const float* p = g_qkv + (size_t)(b * N_ + n) * QKVSTRIDE + c * D_ + h * HD_;
    float x1 = p[d];
    float x2 = p[d + 32];
    float s1, c1, s2, c2;
    sincosf(pe[n * HD_ + d],      &s1, &c1);
    sincosf(pe[n * HD_ + d + 32], &s2, &c2);
    float o1 = x1 * c1 - x2 * s1;
    float o2 = x2 * c2 + x1 * s2;
    if (c == 0) { o1 *= 0.125f; o2 *= 0.125f; }

    size_t dst = ((size_t)(b * H_ + h) * N_ + n) * HD_;
    __nv_bfloat16* dh = (c == 0) ? g_qh : g_kh;
    __nv_bfloat16* dl = (c == 0) ? g_ql : g_kl;
    __nv_bfloat16 h1 = __float2bfloat16(o1);
    __nv_bfloat16 h2 = __float2bfloat16(o2);
    dh[dst + d]      = h1;
    dh[dst + d + 32] = h2;
    dl[dst + d]      = __float2bfloat16(o1 - __bfloat162float(h1));
    dl[dst + d + 32] = __float2bfloat16(o2 - __bfloat162float(h2));
}

// ---------------------------------------------------------------------------
// prep_v: split + transpose V -> [bh][d][n] bf16 (smem tile transpose)
// grid: (ntiles=32, bh=24), 256 threads, tile = 64 n x 64 d
// ---------------------------------------------------------------------------
__global__ void prep_v_kernel()
{
    __shared__ float s[64][68];
    const int tid = threadIdx.x;
    const int bh  = blockIdx.y;
    const int b   = bh / H_;
    const int h   = bh % H_;
    const int n0  = blockIdx.x * 64;

    const float* vbase = g_qkv + (size_t)b * N_ * QKVSTRIDE + 2 * D_ + h * HD_;
#pragma unroll
    for (int f = tid; f < 1024; f += 256) {
        int row = f >> 4;           // n-local
        int c4  = (f & 15) * 4;     // d
        float4 v = *(const float4*)(vbase + (size_t)(n0 + row) * QKVSTRIDE + c4);
        s[row][c4] = v.x; s[row][c4 + 1] = v.y; s[row][c4 + 2] = v.z; s[row][c4 + 3] = v.w;
    }
    __syncthreads();
#pragma unroll
    for (int f = tid; f < 1024; f += 256) {
        int d  = f >> 4;            // d row
        int n4 = (f & 15) * 4;      // n-local
        uint2 ho, lo;
        split2(s[n4][d],     s[n4 + 1][d], ho.x, lo.x);
        split2(s[n4 + 2][d], s[n4 + 3][d], ho.y, lo.y);
        size_t dst = ((size_t)bh * HD_ + d) * N_ + n0 + n4;
        *(uint2*)&g_vh[dst] = ho;
        *(uint2*)&g_vl[dst] = lo;
    }
}

// ---------------------------------------------------------------------------
// Tensor-core flash attention, cp.async double-buffered K/V.
// CTA = 128 queries of one (b,h); 8 warps x 16 q-rows; 16 key tiles of 128.
// ---------------------------------------------------------------------------
#define QKS 72
#define VTS 136
#define A_QT   (128 * QKS)                 // 9216 elems (per Q array)
#define A_KT   (128 * QKS)                 // per K array
#define A_VT   (64 * VTS)                  // 8704 elems per V array
#define A_STG  (2 * A_KT + 2 * A_VT)       // 35840 elems per stage
#define A_SMEM ((2 * A_QT + 2 * A_STG) * 2)  // 180224 bytes

__global__ __launch_bounds__(256, 1) void attn_mma_kernel()
{
    extern __shared__ __nv_bfloat16 smb[];
    __nv_bfloat16* sQh = smb;
    __nv_bfloat16* sQl = smb + A_QT;
    __nv_bfloat16* stage0 = smb + 2 * A_QT;

    const int tid  = threadIdx.x;
    const int lane = tid & 31;
    const int wid  = tid >> 5;
    const int w16  = wid * 16;
    const int bh   = blockIdx.y;
    const int b    = bh / H_;
    const int h    = bh % H_;
    const int q0   = blockIdx.x * 128;

    const __nv_bfloat16* qhb = g_qh + (size_t)bh * N_ * HD_;
    const __nv_bfloat16* qlb = g_ql + (size_t)bh * N_ * HD_;
    const __nv_bfloat16* khb = g_kh + (size_t)bh * N_ * HD_;
    const __nv_bfloat16* klb = g_kl + (size_t)bh * N_ * HD_;
    const __nv_bfloat16* vhb = g_vh + (size_t)bh * HD_ * N_;
    const __nv_bfloat16* vlb = g_vl + (size_t)bh * HD_ * N_;

    // ---- Q tile: plain uint4 loads (contiguous) ----
    for (int f = tid; f < 1024; f += 256) {
        int row = f >> 3;
        int ch  = (f & 7) * 8;
        *(uint4*)&sQh[row * QKS + ch] = *(const uint4*)(qhb + (size_t)(q0 + row) * HD_ + ch);
        *(uint4*)&sQl[row * QKS + ch] = *(const uint4*)(qlb + (size_t)(q0 + row) * HD_ + ch);
    }

    auto load_stage = [&](int st, int kt) {
        __nv_bfloat16* base = stage0 + st * A_STG;
        const int k0 = kt * 128;
        // K: 128 rows x 64 elems (8 chunks/row) per array
        for (int f = tid; f < 1024; f += 256) {
            int row = f >> 3;
            int ch  = (f & 7) * 8;
            size_t g = (size_t)(k0 + row) * HD_ + ch;
            int so = row * QKS + ch;
            cp16(base + so,        khb + g);
            cp16(base + A_KT + so, klb + g);
        }
        // V: 64 rows x 128 elems (16 chunks/row) per array
        __nv_bfloat16* vb = base + 2 * A_KT;
        for (int f = tid; f < 1024; f += 256) {
            int d  = f >> 4;
            int ch = (f & 15) * 8;
            size_t g = (size_t)d * N_ + k0 + ch;
            int so = d * VTS + ch;
            cp16(vb + so,        vhb + g);
            cp16(vb + A_VT + so, vlb + g);
        }
    };

    float oacc[8][4];
#pragma unroll
    for (int ob = 0; ob < 8; ob++)
#pragma unroll
        for (int e = 0; e < 4; e++) oacc[ob][e] = 0.f;
    float m0 = -1e30f, m1 = -1e30f, l0 = 0.f, l1 = 0.f;

    load_stage(0, 0);
    CP_COMMIT();

    for (int kt = 0; kt < N_ / 128; kt++) {
        const int cur = kt & 1;
        if (kt + 1 < N_ / 128) {
            load_stage(cur ^ 1, kt + 1);
            CP_COMMIT();
            CP_WAIT(1);
        } else {
            CP_WAIT(0);
        }
        __syncthreads();

        const __nv_bfloat16* sKh = stage0 + cur * A_STG;
        const __nv_bfloat16* sKl = sKh + A_KT;
        const __nv_bfloat16* sVh = sKh + 2 * A_KT;
        const __nv_bfloat16* sVl = sVh + A_VT;

        // ---- S = Q @ K^T ----
        float sacc[16][4];
#pragma unroll
        for (int nb = 0; nb < 16; nb++)
#pragma unroll
            for (int e = 0; e < 4; e++) sacc[nb][e] = 0.f;

#pragma unroll
        for (int ks = 0; ks < 4; ks++) {
            uint32_t ah[4], al[4];
            const int acol = ks * 16 + (lane >> 4) * 8;
            ldsm_x4(ah, &sQh[(w16 + (lane & 15)) * QKS + acol]);
            ldsm_x4(al, &sQl[(w16 + (lane & 15)) * QKS + acol]);
            const int bcol = ks * 16 + ((lane >> 3) & 1) * 8;
#pragma unroll
            for (int nb = 0; nb < 16; nb++) {
                uint32_t bhf[2], blf[2];
                ldsm_x2(bhf, &sKh[(nb * 8 + (lane & 7)) * QKS + bcol]);
                ldsm_x2(blf, &sKl[(nb * 8 + (lane & 7)) * QKS + bcol]);
                mma16816(sacc[nb], ah, bhf);
                mma16816(sacc[nb], ah, blf);
                mma16816(sacc[nb], al, bhf);
            }
        }

        // ---- online softmax ----
        float mx0 = -1e30f, mx1 = -1e30f;
#pragma unroll
        for (int nb = 0; nb < 16; nb++) {
            mx0 = fmaxf(mx0, fmaxf(sacc[nb][0], sacc[nb][1]));
            mx1 = fmaxf(mx1, fmaxf(sacc[nb][2], sacc[nb][3]));
        }
        mx0 = fmaxf(mx0, __shfl_xor_sync(0xffffffffu, mx0, 1));
        mx0 = fmaxf(mx0, __shfl_xor_sync(0xffffffffu, mx0, 2));
        mx1 = fmaxf(mx1, __shfl_xor_sync(0xffffffffu, mx1, 1));
        mx1 = fmaxf(mx1, __shfl_xor_sync(0xffffffffu, mx1, 2));

        float mn0 = fmaxf(m0, mx0);
        float mn1 = fmaxf(m1, mx1);
        float cr0 = __expf(m0 - mn0);
        float cr1 = __expf(m1 - mn1);
        m0 = mn0; m1 = mn1;

        float rs0 = 0.f, rs1 = 0.f;
#pragma unroll
        for (int nb = 0; nb < 16; nb++) {
            sacc[nb][0] = __expf(sacc[nb][0] - mn0);
            sacc[nb][1] = __expf(sacc[nb][1] - mn0);
            sacc[nb][2] = __expf(sacc[nb][2] - mn1);
            sacc[nb][3] = __expf(sacc[nb][3] - mn1);
            rs0 += sacc[nb][0] + sacc[nb][1];
            rs1 += sacc[nb][2] + sacc[nb][3];
        }
        rs0 += __shfl_xor_sync(0xffffffffu, rs0, 1);
        rs0 += __shfl_xor_sync(0xffffffffu, rs0, 2);
        rs1 += __shfl_xor_sync(0xffffffffu, rs1, 1);
        rs1 += __shfl_xor_sync(0xffffffffu, rs1, 2);
        l0 = l0 * cr0 + rs0;
        l1 = l1 * cr1 + rs1;
#pragma unroll
        for (int ob = 0; ob < 8; ob++) {
            oacc[ob][0] *= cr0; oacc[ob][1] *= cr0;
            oacc[ob][2] *= cr1; oacc[ob][3] *= cr1;
        }

        // ---- pack P into bf16 hi/lo A fragments ----
        uint32_t pah[8][4], pal[8][4];
#pragma unroll
        for (int kb = 0; kb < 8; kb++) {
            split2(sacc[2 * kb][0],     sacc[2 * kb][1],     pah[kb][0], pal[kb][0]);
            split2(sacc[2 * kb][2],     sacc[2 * kb][3],     pah[kb][1], pal[kb][1]);
            split2(sacc[2 * kb + 1][0], sacc[2 * kb + 1][1], pah[kb][2], pal[kb][2]);
            split2(sacc[2 * kb + 1][2], sacc[2 * kb + 1][3], pah[kb][3], pal[kb][3]);
        }

        // ---- O += P @ V ----
#pragma unroll
        for (int ob = 0; ob < 8; ob++) {
#pragma unroll
            for (int kb = 0; kb < 8; kb++) {
                const int bcol = kb * 16 + ((lane >> 3) & 1) * 8;
                uint32_t bhf[2], blf[2];
                ldsm_x2(bhf, &sVh[(ob * 8 + (lane & 7)) * VTS + bcol]);
                ldsm_x2(blf, &sVl[(ob * 8 + (lane & 7)) * VTS + bcol]);
                mma16816(oacc[ob], pah[kb], bhf);
                mma16816(oacc[ob], pah[kb], blf);
                mma16816(oacc[ob], pal[kb], bhf);
            }
        }
        __syncthreads();
    }

    // ---- epilogue ----
    float inv0 = 1.f / l0;
    float inv1 = 1.f / l1;
    const int r0 = q0 + w16 + (lane >> 2);
#pragma unroll
    for (int ob = 0; ob < 8; ob++) {
        int col = h * HD_ + ob * 8 + (lane & 3) * 2;
        float2 v0 = {oacc[ob][0] * inv0, oacc[ob][1] * inv0};
        float2 v1 = {oacc[ob][2] * inv1, oacc[ob][3] * inv1};
        *(float2*)&g_ao[(size_t)(b * N_ + r0) * D_ + col]     = v0;
        *(float2*)&g_ao[(size_t)(b * N_ + r0 + 8) * D_ + col] = v1;
    }
}

// ---------------------------------------------------------------------------
extern "C" void kernel_launch(void* const* d_in, const int* in_sizes, int n_in,
                              void* d_out, int out_size)
{
    const float* x     = (const float*)d_in[0];
    const float* pe    = (const float*)d_in[1];
    const float* Wqkv  = (const float*)d_in[2];
    const float* Wproj = (const float*)d_in[3];
    const float* bproj = (const float*)d_in[4];
    float* out = (float*)d_out;

    float *qkv, *ao;
    __nv_bfloat16 *xh, *xl, *wqh, *wql, *aoh, *aol, *wph, *wpl;
    cudaGetSymbolAddress((void**)&qkv, g_qkv);
    cudaGetSymbolAddress((void**)&ao,  g_ao);
    cudaGetSymbolAddress((void**)&xh,  g_xh);
    cudaGetSymbolAddress((void**)&xl,  g_xl);
    cudaGetSymbolAddress((void**)&wqh, g_wqh);
    cudaGetSymbolAddress((void**)&wql, g_wql);
    cudaGetSymbolAddress((void**)&aoh, g_aoh);
    cudaGetSymbolAddress((void**)&aol, g_aol);
    cudaGetSymbolAddress((void**)&wph, g_wph);
    cudaGetSymbolAddress((void**)&wpl, g_wpl);

    const int M = B_ * N_;           // 4096

    // splits for QKV GEMM
    {
        int n4 = (M * D_) / 4;
        split_bf16_kernel<<<(n4 + 255) / 256, 256>>>((const float4*)x, (uint2*)xh, (uint2*)xl, n4);
        int w4 = (QKVSTRIDE * D_) / 4;
        split_bf16_kernel<<<(w4 + 255) / 256, 256>>>((const float4*)Wqkv, (uint2*)wqh, (uint2*)wql, w4);
    }
    // 1) QKV projection (pipelined)
    {
        cudaFuncSetAttribute(gemm_mma_kernel<false>,
                             cudaFuncAttributeMaxDynamicSharedMemorySize, GEMM_SMEM);
        dim3 grid(QKVSTRIDE / 128, M / 128);
        gemm_mma_kernel<false><<<grid, 256, GEMM_SMEM>>>(xh, xl, wqh, wql, nullptr, qkv,
                                                         M, QKVSTRIDE, D_);
    }
    // 2) prep: RoPE+scale+split Q/K; split+transpose V
    {
        int total = B_ * N_ * 2 * H_ * 32;
        prep_qk_kernel<<<(total + 255) / 256, 256>>>(pe);
        dim3 vg(N_ / 64, BH_);
        prep_v_kernel<<<vg, 256>>>();
    }
    // 3) Attention (tensor-core flash, cp.async pipelined)
    {
        cudaFuncSetAttribute(attn_mma_kernel,
                             cudaFuncAttributeMaxDynamicSharedMemorySize, A_SMEM);
        dim3 grid(N_ / 128, BH_);
        attn_mma_kernel<<<grid, 256, A_SMEM>>>();
    }
    // splits for out projection
    {
        int n4 = (M * D_) / 4;
        split_bf16_kernel<<<(n4 + 255) / 256, 256>>>((const float4*)ao, (uint2*)aoh, (uint2*)aol, n4);
        int w4 = (D_ * D_) / 4;
        split_bf16_kernel<<<(w4 + 255) / 256, 256>>>((const float4*)Wproj, (uint2*)wph, (uint2*)wpl, w4);
    }
    // 4) output projection (pipelined)
    {
        cudaFuncSetAttribute(gemm_mma_kernel<true>,
                             cudaFuncAttributeMaxDynamicSharedMemorySize, GEMM_SMEM);
        dim3 grid(D_ / 128, M / 128);
        gemm_mma_kernel<true><<<grid, 256, GEMM_SMEM>>>(aoh, aol, wph, wpl, bproj, out,
                                                        M, D_, D_);
    }
}